// round 15
// baseline (speedup 1.0000x reference)
#include <cuda_runtime.h>
#include <stdint.h>

// Embedding gather: out[j*64+k] = pages[idx[j]*64+k]
// pages [8,125000,64] contiguous; (i/P)*P + i%P == i -> flat gather at idx[j]*64.
// indices int32 (JAX default x64-disabled).
//
// R2-R11 established: all load-path variants pin at ~11us with HBM at
// ~2.9TB/s = the DRAM random-row (bank-bound) ceiling for 256B gathers, and
// warm==cold, i.e. the table is NOT staying L2-resident across graph
// replays. This round forces residency:
//   - table reads: ld.global.nc.L2::evict_last.v4.b64 (32B, pin in L2)
//   - output:      st.global.cs (evict-first streaming, no L2 churn)
// on the R3 phase structure (ILP=4, all idx loads -> all gathers -> stores).
// 8 threads cover one 256B row; idx load uniform per 8-thread group.

#define N_WORDS 1000000
#define ILP 4
#define THREADS 256

struct v4b64 { unsigned long long a, b, c, d; };   // 32 bytes

__device__ __forceinline__ v4b64 ldg_evict_last_32B(const void* p) {
    v4b64 v;
    asm volatile("ld.global.nc.L2::evict_last.v4.b64 {%0,%1,%2,%3}, [%4];"
                 : "=l"(v.a), "=l"(v.b), "=l"(v.c), "=l"(v.d) : "l"(p));
    return v;
}

__device__ __forceinline__ void st_cs_32B(void* p, const v4b64& v) {
    // streaming (evict-first) stores; 2 x 16B .cs (256-bit st has no .cs form)
    asm volatile("st.global.cs.v2.b64 [%0], {%1,%2};"
                 :: "l"(p), "l"(v.a), "l"(v.b) : "memory");
    asm volatile("st.global.cs.v2.b64 [%0+16], {%1,%2};"
                 :: "l"(p), "l"(v.c), "l"(v.d) : "memory");
}

__global__ void __launch_bounds__(THREADS) emb_gather_kernel(
        const int* __restrict__ idx,
        const char* __restrict__ pages,
        char* __restrict__ out,
        unsigned n_chunks) {               // 32B chunks = n_lookups * 8
    const unsigned S = gridDim.x * THREADS;        // grid stride (mult of 8)
    const unsigned t0 = blockIdx.x * THREADS + threadIdx.x;
    const unsigned c = (t0 & 7u) * 32u;            // byte offset in row

    unsigned off[ILP];
    bool ok[ILP];

    // Phase 1: independent idx loads + offset math
    #pragma unroll
    for (int u = 0; u < ILP; u++) {
        unsigned t = t0 + u * S;
        ok[u] = (t < n_chunks);
        unsigned j = t >> 3;                        // lookup id
        int iv = ok[u] ? __ldg(&idx[j]) : 0;
        iv = max(0, min(iv, N_WORDS - 1));          // defensive clamp
        off[u] = (unsigned)iv * 256u + c;
    }

    // Phase 2: independent 32B gathers, evict-last (pin table in L2)
    v4b64 d[ILP];
    #pragma unroll
    for (int u = 0; u < ILP; u++)
        d[u] = ldg_evict_last_32B(pages + off[u]);

    // Phase 3: streaming stores (evict-first; zero L2 churn from output)
    #pragma unroll
    for (int u = 0; u < ILP; u++)
        if (ok[u]) st_cs_32B(out + (size_t)(t0 + u * S) * 32u, d[u]);
}

extern "C" void kernel_launch(void* const* d_in, const int* in_sizes, int n_in,
                              void* d_out, int out_size) {
    const int*  idx   = (const int*)d_in[0];    // [16,8192] int32
    const char* pages = (const char*)d_in[1];   // [8,125000,64] fp32, 256B rows

    unsigned n_lookups = (unsigned)in_sizes[0]; // 131072
    unsigned n_chunks = n_lookups * 8u;         // 1,048,576 x 32B

    const unsigned chunk = THREADS * ILP;       // 1024 per block
    unsigned blocks = (n_chunks + chunk - 1) / chunk;   // 1024

    emb_gather_kernel<<<blocks, THREADS>>>(idx, pages, (char*)d_out, n_chunks);
}